// round 2
// baseline (speedup 1.0000x reference)
#include <cuda_runtime.h>

#define HH 256
#define WW 256
#define NT 16
#define NB 8
#define NIMG (NB*NT)
#define HW (HH*WW)
#define SAMPLE_ELEMS (NT*HW)          // 1048576
#define WIN 11
#define PADW 5
#define SPLIT 4
#define SEG (HH/SPLIT)                // 64
#define NLOADS (SEG + 10)             // 74 row loads per segment
#define RED_BLKS 64
#define SSIM_EPS 1e-6f
#define C1_ (1.0e-4f)
#define C2_ (9.0e-4f)
#define C3_ (4.5e-4f)

// scratch (no allocations allowed)
__device__ float g_partial[5 * NB * RED_BLKS];   // stat-major: pmn,pmx,tmn,tmx,tsum
__device__ float g_params[NB * 4];               // mnt, invt, mnp, invp
__device__ float g_valid[NB];
__device__ float g_ssim[NB];
__device__ float g_w[WIN];

// ---------------------------------------------------------------------------
// Kernel 1: per-sample min/max of pred & tgt, sum of tgt. 64 blocks / sample.
// ---------------------------------------------------------------------------
__global__ __launch_bounds__(256) void reduce_kernel(const float* __restrict__ pred,
                                                     const float* __restrict__ tgt) {
    int b   = blockIdx.x >> 6;
    int blk = blockIdx.x & 63;
    int tid = threadIdx.x;

    const float4* p4 = (const float4*)(pred + (size_t)b * SAMPLE_ELEMS + (size_t)blk * 16384);
    const float4* t4 = (const float4*)(tgt  + (size_t)b * SAMPLE_ELEMS + (size_t)blk * 16384);

    float pmn = 1e30f, pmx = -1e30f, tmn = 1e30f, tmx = -1e30f, ts = 0.f;
    #pragma unroll 4
    for (int i = tid; i < 4096; i += 256) {
        float4 a = p4[i];
        pmn = fminf(pmn, fminf(fminf(a.x, a.y), fminf(a.z, a.w)));
        pmx = fmaxf(pmx, fmaxf(fmaxf(a.x, a.y), fmaxf(a.z, a.w)));
        float4 c = t4[i];
        tmn = fminf(tmn, fminf(fminf(c.x, c.y), fminf(c.z, c.w)));
        tmx = fmaxf(tmx, fmaxf(fmaxf(c.x, c.y), fmaxf(c.z, c.w)));
        ts += (c.x + c.y) + (c.z + c.w);
    }
    // warp reduce
    #pragma unroll
    for (int o = 16; o; o >>= 1) {
        pmn = fminf(pmn, __shfl_xor_sync(~0u, pmn, o));
        pmx = fmaxf(pmx, __shfl_xor_sync(~0u, pmx, o));
        tmn = fminf(tmn, __shfl_xor_sync(~0u, tmn, o));
        tmx = fmaxf(tmx, __shfl_xor_sync(~0u, tmx, o));
        ts += __shfl_xor_sync(~0u, ts, o);
    }
    __shared__ float sm[8 * 5];
    int wid = tid >> 5;
    if ((tid & 31) == 0) {
        sm[wid * 5 + 0] = pmn; sm[wid * 5 + 1] = pmx;
        sm[wid * 5 + 2] = tmn; sm[wid * 5 + 3] = tmx;
        sm[wid * 5 + 4] = ts;
    }
    __syncthreads();
    if (tid == 0) {
        float a0 = sm[0], a1 = sm[1], a2 = sm[2], a3 = sm[3], a4 = sm[4];
        #pragma unroll
        for (int w = 1; w < 8; ++w) {
            a0 = fminf(a0, sm[w * 5 + 0]);
            a1 = fmaxf(a1, sm[w * 5 + 1]);
            a2 = fminf(a2, sm[w * 5 + 2]);
            a3 = fmaxf(a3, sm[w * 5 + 3]);
            a4 += sm[w * 5 + 4];
        }
        int base = b * RED_BLKS + blk;
        g_partial[0 * NB * RED_BLKS + base] = a0;
        g_partial[1 * NB * RED_BLKS + base] = a1;
        g_partial[2 * NB * RED_BLKS + base] = a2;
        g_partial[3 * NB * RED_BLKS + base] = a3;
        g_partial[4 * NB * RED_BLKS + base] = a4;
    }
}

// ---------------------------------------------------------------------------
// Kernel 2: fold partials -> per-sample norm params; init accumulators;
//           compute gaussian weights (match reference float32 math).
// ---------------------------------------------------------------------------
__global__ void finalize_kernel() {
    int b = blockIdx.x;
    int tid = threadIdx.x;     // 64 threads
    float pmn = g_partial[0 * NB * RED_BLKS + b * RED_BLKS + tid];
    float pmx = g_partial[1 * NB * RED_BLKS + b * RED_BLKS + tid];
    float tmn = g_partial[2 * NB * RED_BLKS + b * RED_BLKS + tid];
    float tmx = g_partial[3 * NB * RED_BLKS + b * RED_BLKS + tid];
    float ts  = g_partial[4 * NB * RED_BLKS + b * RED_BLKS + tid];
    #pragma unroll
    for (int o = 16; o; o >>= 1) {
        pmn = fminf(pmn, __shfl_xor_sync(~0u, pmn, o));
        pmx = fmaxf(pmx, __shfl_xor_sync(~0u, pmx, o));
        tmn = fminf(tmn, __shfl_xor_sync(~0u, tmn, o));
        tmx = fmaxf(tmx, __shfl_xor_sync(~0u, tmx, o));
        ts += __shfl_xor_sync(~0u, ts, o);
    }
    __shared__ float sm[2 * 5];
    if ((tid & 31) == 0) {
        int w = tid >> 5;
        sm[w * 5 + 0] = pmn; sm[w * 5 + 1] = pmx; sm[w * 5 + 2] = tmn;
        sm[w * 5 + 3] = tmx; sm[w * 5 + 4] = ts;
    }
    __syncthreads();
    if (tid == 0) {
        pmn = fminf(sm[0], sm[5]); pmx = fmaxf(sm[1], sm[6]);
        tmn = fminf(sm[2], sm[7]); tmx = fmaxf(sm[3], sm[8]);
        ts  = sm[4] + sm[9];
        float invp = 1.0f / fmaxf(pmx - pmn, SSIM_EPS);
        float invt = 1.0f / fmaxf(tmx - tmn, SSIM_EPS);
        g_params[b * 4 + 0] = tmn;
        g_params[b * 4 + 1] = invt;
        g_params[b * 4 + 2] = pmn;
        g_params[b * 4 + 3] = invp;
        g_valid[b] = (ts != 0.0f) ? 1.0f : 0.0f;
        g_ssim[b]  = 0.0f;
        if (b == 0) {
            float g[WIN]; float s = 0.f;
            #pragma unroll
            for (int i = 0; i < WIN; ++i) {
                float d = (float)i - 5.0f;
                g[i] = expf(-d * d / 4.5f);
                s += g[i];
            }
            #pragma unroll
            for (int i = 0; i < WIN; ++i) g_w[i] = g[i] / s;
        }
    }
}

// ---------------------------------------------------------------------------
// Kernel 3: fused normalize + separable 11x11 gauss conv (5 fields) + SSIM.
// One thread per image column; column-streaming with an 11-deep register ring.
// Ring indices are compile-time: row loop unrolled in chunks of 11.
// ---------------------------------------------------------------------------
__global__ __launch_bounds__(256, 2) void conv_kernel(const float* __restrict__ pred,
                                                      const float* __restrict__ tgt) {
    int n   = blockIdx.x / SPLIT;     // image (b*16+t)
    int seg = blockIdx.x % SPLIT;
    int b   = n >> 4;
    int tid = threadIdx.x;            // column x

    float mnt  = g_params[b * 4 + 0];
    float invt = g_params[b * 4 + 1];
    float mnp  = g_params[b * 4 + 2];
    float invp = g_params[b * 4 + 3];
    float w[WIN];
    #pragma unroll
    for (int k = 0; k < WIN; ++k) w[k] = g_w[k];

    __shared__ float s_t[WW + 2 * PADW + 6];
    __shared__ float s_p[WW + 2 * PADW + 6];
    if (tid < PADW) {
        s_t[tid] = 0.f; s_p[tid] = 0.f;
        s_t[PADW + WW + tid] = 0.f; s_p[PADW + WW + tid] = 0.f;
    }

    int r0 = seg * SEG;
    const float* tb = tgt  + (size_t)n * HW;
    const float* pb = pred + (size_t)n * HW;

    float rt[WIN], rp[WIN], rtt[WIN], rpp[WIN], rtp[WIN];
    float acc = 0.f;

    for (int base = 0; base < 77; base += 11) {
        #pragma unroll
        for (int u = 0; u < 11; ++u) {
            int i = base + u;                 // load index
            int y = r0 - PADW + i;            // source row
            bool live  = (i < NLOADS);
            bool inimg = live && (y >= 0) && (y < HH);

            __syncthreads();
            if (inimg) {
                int idx = y * WW + tid;
                s_t[PADW + tid] = (tb[idx] - mnt) * invt;
                s_p[PADW + tid] = (pb[idx] - mnp) * invp;
            }
            __syncthreads();

            float at = 0.f, ap = 0.f, att = 0.f, app = 0.f, atp = 0.f;
            if (inimg) {
                #pragma unroll
                for (int k = 0; k < WIN; ++k) {
                    float tv = s_t[tid + k];
                    float pv = s_p[tid + k];
                    float wt = w[k] * tv;
                    float wp = w[k] * pv;
                    at += wt; ap += wp;
                    att = fmaf(wt, tv, att);
                    app = fmaf(wp, pv, app);
                    atp = fmaf(wt, pv, atp);
                }
            }
            rt[u] = at; rp[u] = ap; rtt[u] = att; rpp[u] = app; rtp[u] = atp;

            if (i >= 10 && live) {
                // output row oy = r0 + i - 10
                float ct = 0.f, cp = 0.f, ctt = 0.f, cpp = 0.f, ctp = 0.f;
                #pragma unroll
                for (int s = 0; s < 11; ++s) {
                    int d = (s - u + 10) % 11;       // compile-time per (u,s)
                    float wd = w[d];
                    ct  = fmaf(wd, rt[s],  ct);
                    cp  = fmaf(wd, rp[s],  cp);
                    ctt = fmaf(wd, rtt[s], ctt);
                    cpp = fmaf(wd, rpp[s], cpp);
                    ctp = fmaf(wd, rtp[s], ctp);
                }
                float mu1  = ct, mu2 = cp;
                float mu1s = mu1 * mu1;
                float mu2s = mu2 * mu2;
                float mu12 = mu1 * mu2;
                float s1   = fmaxf(ctt - mu1s, SSIM_EPS);
                float s2   = fmaxf(cpp - mu2s, SSIM_EPS);
                float s12  = ctp - mu12;
                float root = sqrtf(s1 * s2);
                float lum  = __fdividef(2.0f * mu12 + C1_, mu1s + mu2s + C1_);
                float con  = __fdividef(2.0f * root + C2_, s1 + s2 + C2_);
                float str  = __fdividef(s12 + C3_, root + C3_);
                acc += lum * con * str;
            }
        }
    }

    // block reduce + single atomic
    #pragma unroll
    for (int o = 16; o; o >>= 1) acc += __shfl_xor_sync(~0u, acc, o);
    __shared__ float red[8];
    if ((tid & 31) == 0) red[tid >> 5] = acc;
    __syncthreads();
    if (tid == 0) {
        float t = red[0];
        #pragma unroll
        for (int ww = 1; ww < 8; ++ww) t += red[ww];
        atomicAdd(&g_ssim[b], t);
    }
}

// ---------------------------------------------------------------------------
// Kernel 4: combine to scalar loss.
// ---------------------------------------------------------------------------
__global__ void final_kernel(float* __restrict__ out, int out_size) {
    int tid = threadIdx.x;
    float v = 0.f, s = 0.f;
    if (tid < NB) {
        v = g_valid[tid];
        s = (1.0f - g_ssim[tid] * (1.0f / (float)SAMPLE_ELEMS)) * v;
    }
    #pragma unroll
    for (int o = 16; o; o >>= 1) {
        s += __shfl_xor_sync(~0u, s, o);
        v += __shfl_xor_sync(~0u, v, o);
    }
    if (tid == 0) {
        float loss = s / fmaxf(v, 1.0f);
        for (int i = 0; i < out_size; ++i) out[i] = loss;
    }
}

extern "C" void kernel_launch(void* const* d_in, const int* in_sizes, int n_in,
                              void* d_out, int out_size) {
    const float* pred = (const float*)d_in[0];
    const float* tgt  = (const float*)d_in[1];
    float* out = (float*)d_out;

    reduce_kernel<<<NB * RED_BLKS, 256>>>(pred, tgt);
    finalize_kernel<<<NB, 64>>>();
    conv_kernel<<<NIMG * SPLIT, 256>>>(pred, tgt);
    final_kernel<<<1, 32>>>(out, out_size);
}

// round 6
// speedup vs baseline: 1.2725x; 1.2725x over previous
#include <cuda_runtime.h>

#define HH 256
#define WW 256
#define NT 16
#define NB 8
#define NIMG (NB*NT)
#define HW (HH*WW)
#define SAMPLE_ELEMS (NT*HW)          // 1048576
#define WIN 11
#define PADW 5
#define SPLIT 2
#define SEG (HH/SPLIT)                // 128
#define NLOADS (SEG + 10)             // 138 row loads per segment
#define RED_BLKS 64
#define SSIM_EPS 1e-6f
#define C1_ (1.0e-4f)
#define C2_ (9.0e-4f)
#define C3_ (4.5e-4f)

// canonical 11-tap sigma=1.5 gaussian (matches float32 expf to <1ulp-ish)
#define GW0 0.0010283799f
#define GW1 0.0075987583f
#define GW2 0.0360007723f
#define GW3 0.1093606947f
#define GW4 0.2130055329f
#define GW5 0.2660117190f

// scratch (no allocations allowed)
__device__ float g_partial[5 * NB * RED_BLKS];   // stat-major: pmn,pmx,tmn,tmx,tsum
__device__ float g_params[NB * 4];               // mnt, invt, mnp, invp
__device__ float g_valid[NB];
__device__ float g_ssim[NB];

// ---------------------------------------------------------------------------
// Kernel 1: per-sample min/max of pred & tgt, sum of tgt. 64 blocks / sample.
// ---------------------------------------------------------------------------
__global__ __launch_bounds__(256) void reduce_kernel(const float* __restrict__ pred,
                                                     const float* __restrict__ tgt) {
    int b   = blockIdx.x >> 6;
    int blk = blockIdx.x & 63;
    int tid = threadIdx.x;

    const float4* p4 = (const float4*)(pred + (size_t)b * SAMPLE_ELEMS + (size_t)blk * 16384);
    const float4* t4 = (const float4*)(tgt  + (size_t)b * SAMPLE_ELEMS + (size_t)blk * 16384);

    float pmn = 1e30f, pmx = -1e30f, tmn = 1e30f, tmx = -1e30f, ts = 0.f;
    #pragma unroll 4
    for (int i = tid; i < 4096; i += 256) {
        float4 a = p4[i];
        pmn = fminf(pmn, fminf(fminf(a.x, a.y), fminf(a.z, a.w)));
        pmx = fmaxf(pmx, fmaxf(fmaxf(a.x, a.y), fmaxf(a.z, a.w)));
        float4 c = t4[i];
        tmn = fminf(tmn, fminf(fminf(c.x, c.y), fminf(c.z, c.w)));
        tmx = fmaxf(tmx, fmaxf(fmaxf(c.x, c.y), fmaxf(c.z, c.w)));
        ts += (c.x + c.y) + (c.z + c.w);
    }
    #pragma unroll
    for (int o = 16; o; o >>= 1) {
        pmn = fminf(pmn, __shfl_xor_sync(~0u, pmn, o));
        pmx = fmaxf(pmx, __shfl_xor_sync(~0u, pmx, o));
        tmn = fminf(tmn, __shfl_xor_sync(~0u, tmn, o));
        tmx = fmaxf(tmx, __shfl_xor_sync(~0u, tmx, o));
        ts += __shfl_xor_sync(~0u, ts, o);
    }
    __shared__ float sm[8 * 5];
    int wid = tid >> 5;
    if ((tid & 31) == 0) {
        sm[wid * 5 + 0] = pmn; sm[wid * 5 + 1] = pmx;
        sm[wid * 5 + 2] = tmn; sm[wid * 5 + 3] = tmx;
        sm[wid * 5 + 4] = ts;
    }
    __syncthreads();
    if (tid == 0) {
        float a0 = sm[0], a1 = sm[1], a2 = sm[2], a3 = sm[3], a4 = sm[4];
        #pragma unroll
        for (int w = 1; w < 8; ++w) {
            a0 = fminf(a0, sm[w * 5 + 0]);
            a1 = fmaxf(a1, sm[w * 5 + 1]);
            a2 = fminf(a2, sm[w * 5 + 2]);
            a3 = fmaxf(a3, sm[w * 5 + 3]);
            a4 += sm[w * 5 + 4];
        }
        int base = b * RED_BLKS + blk;
        g_partial[0 * NB * RED_BLKS + base] = a0;
        g_partial[1 * NB * RED_BLKS + base] = a1;
        g_partial[2 * NB * RED_BLKS + base] = a2;
        g_partial[3 * NB * RED_BLKS + base] = a3;
        g_partial[4 * NB * RED_BLKS + base] = a4;
    }
}

// ---------------------------------------------------------------------------
// Kernel 2: fold partials -> per-sample norm params; init accumulators.
// ---------------------------------------------------------------------------
__global__ void finalize_kernel() {
    int b = blockIdx.x;
    int tid = threadIdx.x;     // 64 threads
    float pmn = g_partial[0 * NB * RED_BLKS + b * RED_BLKS + tid];
    float pmx = g_partial[1 * NB * RED_BLKS + b * RED_BLKS + tid];
    float tmn = g_partial[2 * NB * RED_BLKS + b * RED_BLKS + tid];
    float tmx = g_partial[3 * NB * RED_BLKS + b * RED_BLKS + tid];
    float ts  = g_partial[4 * NB * RED_BLKS + b * RED_BLKS + tid];
    #pragma unroll
    for (int o = 16; o; o >>= 1) {
        pmn = fminf(pmn, __shfl_xor_sync(~0u, pmn, o));
        pmx = fmaxf(pmx, __shfl_xor_sync(~0u, pmx, o));
        tmn = fminf(tmn, __shfl_xor_sync(~0u, tmn, o));
        tmx = fmaxf(tmx, __shfl_xor_sync(~0u, tmx, o));
        ts += __shfl_xor_sync(~0u, ts, o);
    }
    __shared__ float sm[2 * 5];
    if ((tid & 31) == 0) {
        int w = tid >> 5;
        sm[w * 5 + 0] = pmn; sm[w * 5 + 1] = pmx; sm[w * 5 + 2] = tmn;
        sm[w * 5 + 3] = tmx; sm[w * 5 + 4] = ts;
    }
    __syncthreads();
    if (tid == 0) {
        pmn = fminf(sm[0], sm[5]); pmx = fmaxf(sm[1], sm[6]);
        tmn = fminf(sm[2], sm[7]); tmx = fmaxf(sm[3], sm[8]);
        ts  = sm[4] + sm[9];
        float invp = 1.0f / fmaxf(pmx - pmn, SSIM_EPS);
        float invt = 1.0f / fmaxf(tmx - tmn, SSIM_EPS);
        g_params[b * 4 + 0] = tmn;
        g_params[b * 4 + 1] = invt;
        g_params[b * 4 + 2] = pmn;
        g_params[b * 4 + 3] = invp;
        g_valid[b] = (ts != 0.0f) ? 1.0f : 0.0f;
        g_ssim[b]  = 0.0f;
    }
}

// ---------------------------------------------------------------------------
// Kernel 3: fused normalize + separable 11x11 gauss conv (5 fields) + SSIM.
// One thread per column. Immediate-form FFMA (compile-time weights),
// interleaved {t,p} float2 smem rows (LDS.64), rotating 2-slot row buffer
// with a single barrier per row, 11-deep compile-time register ring.
// ---------------------------------------------------------------------------
__global__ __launch_bounds__(256, 2) void conv_kernel(const float* __restrict__ pred,
                                                      const float* __restrict__ tgt) {
    const float w[WIN] = {GW0, GW1, GW2, GW3, GW4, GW5, GW4, GW3, GW2, GW1, GW0};

    int n   = blockIdx.x >> 1;        // image (b*16+t)
    int seg = blockIdx.x & 1;
    int b   = n >> 4;
    int tid = threadIdx.x;            // column x

    float mnt  = g_params[b * 4 + 0];
    float invt = g_params[b * 4 + 1];
    float mnp  = g_params[b * 4 + 2];
    float invp = g_params[b * 4 + 3];

    // interleaved row buffers: slot [2], entries = {t_norm, p_norm} per column,
    // image columns at [5..260], zero borders at [0..4] and [261..265].
    __shared__ float2 sb[2][WW + 2 * PADW + 2];
    if (tid < PADW) {
        float2 z = make_float2(0.f, 0.f);
        sb[0][tid] = z; sb[1][tid] = z;
        sb[0][PADW + WW + tid] = z; sb[1][PADW + WW + tid] = z;
    }
    __syncthreads();

    int r0 = seg * SEG;
    const float* tb = tgt  + (size_t)n * HW;
    const float* pb = pred + (size_t)n * HW;

    float rt[WIN], rp[WIN], rtt[WIN], rpp[WIN], rtp[WIN];
    float acc = 0.f;

    #pragma unroll 1
    for (int base = 0; base < 143; base += 11) {
        #pragma unroll
        for (int u = 0; u < 11; ++u) {
            int i = base + u;                 // load index
            int y = r0 - PADW + i;            // source row
            bool live  = (i < NLOADS);
            bool inimg = live && (y >= 0) && (y < HH);
            int slot = i & 1;

            if (inimg) {
                int idx = y * WW + tid;
                float tn = (tb[idx] - mnt) * invt;
                float pn = (pb[idx] - mnp) * invp;
                sb[slot][PADW + tid] = make_float2(tn, pn);
            }
            __syncthreads();

            float at = 0.f, ap = 0.f, att = 0.f, app = 0.f, atp = 0.f;
            if (inimg) {
                const float2* row = sb[slot] + tid;
                #pragma unroll
                for (int k = 0; k < WIN; ++k) {
                    float2 m = row[k];          // LDS.64, 8B aligned
                    float wk = w[k];            // immediate after unroll
                    at  = fmaf(wk, m.x, at);    // FFMA-imm
                    ap  = fmaf(wk, m.y, ap);    // FFMA-imm
                    float wt = wk * m.x;        // FMUL-imm
                    float wp = wk * m.y;        // FMUL-imm
                    att = fmaf(wt, m.x, att);
                    app = fmaf(wp, m.y, app);
                    atp = fmaf(wt, m.y, atp);
                }
            }
            rt[u] = at; rp[u] = ap; rtt[u] = att; rpp[u] = app; rtp[u] = atp;

            if (i >= 10 && live) {
                // output row oy = r0 + i - 10
                float ct = 0.f, cp = 0.f, ctt = 0.f, cpp = 0.f, ctp = 0.f;
                #pragma unroll
                for (int s = 0; s < 11; ++s) {
                    int d = (s - u + 10) % 11;       // compile-time per (u,s)
                    float wd = w[d];                 // immediate
                    ct  = fmaf(wd, rt[s],  ct);      // FFMA-imm
                    cp  = fmaf(wd, rp[s],  cp);
                    ctt = fmaf(wd, rtt[s], ctt);
                    cpp = fmaf(wd, rpp[s], cpp);
                    ctp = fmaf(wd, rtp[s], ctp);
                }
                float mu1  = ct, mu2 = cp;
                float mu1s = mu1 * mu1;
                float mu2s = mu2 * mu2;
                float mu12 = mu1 * mu2;
                float s1   = fmaxf(ctt - mu1s, SSIM_EPS);
                float s2   = fmaxf(cpp - mu2s, SSIM_EPS);
                float s12  = ctp - mu12;
                float root = sqrtf(s1 * s2);
                float lum  = __fdividef(2.0f * mu12 + C1_, mu1s + mu2s + C1_);
                float con  = __fdividef(2.0f * root + C2_, s1 + s2 + C2_);
                float str  = __fdividef(s12 + C3_, root + C3_);
                acc += lum * con * str;
            }
        }
    }

    // block reduce + single atomic
    #pragma unroll
    for (int o = 16; o; o >>= 1) acc += __shfl_xor_sync(~0u, acc, o);
    __shared__ float red[8];
    if ((tid & 31) == 0) red[tid >> 5] = acc;
    __syncthreads();
    if (tid == 0) {
        float t = red[0];
        #pragma unroll
        for (int ww = 1; ww < 8; ++ww) t += red[ww];
        atomicAdd(&g_ssim[b], t);
    }
}

// ---------------------------------------------------------------------------
// Kernel 4: combine to scalar loss.
// ---------------------------------------------------------------------------
__global__ void final_kernel(float* __restrict__ out, int out_size) {
    int tid = threadIdx.x;
    float v = 0.f, s = 0.f;
    if (tid < NB) {
        v = g_valid[tid];
        s = (1.0f - g_ssim[tid] * (1.0f / (float)SAMPLE_ELEMS)) * v;
    }
    #pragma unroll
    for (int o = 16; o; o >>= 1) {
        s += __shfl_xor_sync(~0u, s, o);
        v += __shfl_xor_sync(~0u, v, o);
    }
    if (tid == 0) {
        float loss = s / fmaxf(v, 1.0f);
        for (int i = 0; i < out_size; ++i) out[i] = loss;
    }
}

extern "C" void kernel_launch(void* const* d_in, const int* in_sizes, int n_in,
                              void* d_out, int out_size) {
    const float* pred = (const float*)d_in[0];
    const float* tgt  = (const float*)d_in[1];
    float* out = (float*)d_out;

    reduce_kernel<<<NB * RED_BLKS, 256>>>(pred, tgt);
    finalize_kernel<<<NB, 64>>>();
    conv_kernel<<<NIMG * SPLIT, 256>>>(pred, tgt);
    final_kernel<<<1, 32>>>(out, out_size);
}